// round 15
// baseline (speedup 1.0000x reference)
#include <cuda_runtime.h>
#include <cuda_fp16.h>
#include <cstdint>
#include <math.h>

#define F    1024
#define MAXN 10000
#define MAXE 80000
#define NG   64
#define DD   128

// ---------------- static device scratch ----------------
__device__ __half g_x16[2][(size_t)MAXN * F];    // fp16(x)
__device__ __half g_y16[2][(size_t)MAXN * F];    // fp16(leaky(agg@W + b))
__device__ __half g_a16[2][(size_t)MAXN * F];    // fp16(agg)
__device__ __half g_wh[2][(size_t)F * F];        // fp16(W^T)  [n][k]
__device__ int   g_deg[2][MAXN];
__device__ float g_dinv[2][MAXN];
__device__ int   g_rowptr[2][MAXN + 1];
__device__ int   g_cursor[2][MAXN];
__device__ int   g_col[2][MAXE];
__device__ int   g_goff[2][NG + 1];
__device__ float g_pool[2][NG * F];
__device__ int   g_is64[4];   // 0: edge b0, 1: batch b0, 2: edge b1, 3: batch b1

__device__ __forceinline__ float leaky(float v) { return v >= 0.0f ? v : 0.01f * v; }

__device__ __forceinline__ int idx_at(const void* p, long long i, int is64) {
    return is64 ? (int)(((const long long*)p)[i]) : ((const int*)p)[i];
}

// ---------------- low-level helpers ----------------
__device__ __forceinline__ uint32_t smem_to_u32(const void* smem_ptr) {
    uint32_t addr;
    asm("{ .reg .u64 tmp; cvta.to.shared.u64 tmp, %1; cvt.u32.u64 %0, tmp; }"
        : "=r"(addr) : "l"(smem_ptr));
    return addr;
}
__device__ __forceinline__ void cp_async16(uint32_t dst, const void* src, bool p) {
    asm volatile("cp.async.cg.shared.global [%0], [%1], 16, %2;"
                 :: "r"(dst), "l"(src), "r"(p ? 16u : 0u) : "memory");
}
__device__ __forceinline__ void cp_commit() {
    asm volatile("cp.async.commit_group;" ::: "memory");
}
template <int N>
__device__ __forceinline__ void cp_wait() {
    asm volatile("cp.async.wait_group %0;" :: "n"(N) : "memory");
}
__device__ __forceinline__ uint32_t lds32(uint32_t addr) {
    uint32_t v;
    asm volatile("ld.shared.b32 %0, [%1];" : "=r"(v) : "r"(addr));
    return v;
}
__device__ __forceinline__ void mma16816(float* c, const uint32_t* a, const uint32_t* b) {
    asm volatile(
        "mma.sync.aligned.m16n8k16.row.col.f32.f16.f16.f32 "
        "{%0,%1,%2,%3}, {%4,%5,%6,%7}, {%8,%9}, {%0,%1,%2,%3};"
        : "+f"(c[0]), "+f"(c[1]), "+f"(c[2]), "+f"(c[3])
        : "r"(a[0]), "r"(a[1]), "r"(a[2]), "r"(a[3]), "r"(b[0]), "r"(b[1]));
}

// ---------------- k_pre: dtype detect (tail-scan) + deg zeroing ----------------
__global__ void k_pre(const unsigned int* p0, const unsigned int* p1,
                      const unsigned int* p2, const unsigned int* p3,
                      int nw0, int nw1, int nw2, int nw3) {
    if (blockIdx.x < 4) {
        const unsigned int* p; int nw;
        if (blockIdx.x == 0)      { p = p0; nw = nw0; }
        else if (blockIdx.x == 1) { p = p1; nw = nw1; }
        else if (blockIdx.x == 2) { p = p2; nw = nw2; }
        else                      { p = p3; nw = nw3; }
        int start = nw > 4096 ? nw - 4096 : 0;
        __shared__ unsigned int sh[256];
        unsigned int acc = 0;
        for (int i = start + threadIdx.x; i < nw; i += 256)
            if (i & 1) acc |= p[i];
        sh[threadIdx.x] = acc;
        __syncthreads();
        for (int s = 128; s > 0; s >>= 1) {
            if (threadIdx.x < s) sh[threadIdx.x] |= sh[threadIdx.x + s];
            __syncthreads();
        }
        if (threadIdx.x == 0) g_is64[blockIdx.x] = (sh[0] == 0u) ? 1 : 0;
    } else {
        int i = (blockIdx.x - 4) * 256 + threadIdx.x;
        if (i < 2 * MAXN) ((int*)g_deg)[i] = 0;
    }
}

// ---------------- per-branch degree histogram (4 edges/thread) ----------------
__global__ void k_deg1(const void* __restrict__ ei, int E, int slot, int b) {
    int is64 = g_is64[slot];
    int e = (blockIdx.x * blockDim.x + threadIdx.x) * 4;
    if (e + 4 <= E) {
        int d0 = idx_at(ei, (long long)E + e + 0, is64);
        int d1 = idx_at(ei, (long long)E + e + 1, is64);
        int d2 = idx_at(ei, (long long)E + e + 2, is64);
        int d3 = idx_at(ei, (long long)E + e + 3, is64);
        atomicAdd(&g_deg[b][d0], 1);
        atomicAdd(&g_deg[b][d1], 1);
        atomicAdd(&g_deg[b][d2], 1);
        atomicAdd(&g_deg[b][d3], 1);
    } else {
        for (int i = e; i < E; i++)
            atomicAdd(&g_deg[b][idx_at(ei, (long long)E + i, is64)], 1);
    }
}

// ---------------- per-branch single-pass scan (+dinv) and goff ----------------
__global__ __launch_bounds__(1024)
void k_scan1(int N, int b, const void* __restrict__ batch, int bslot, int vpt) {
    if (blockIdx.x == 1) {
        int g = threadIdx.x;
        if (g > NG) return;
        int is64 = g_is64[bslot];
        int lo = 0, hi = N;
        while (lo < hi) {
            int mid = (lo + hi) >> 1;
            if (idx_at(batch, mid, is64) < g) lo = mid + 1; else hi = mid;
        }
        g_goff[b][g] = lo;
        return;
    }
    __shared__ int wsum[32];
    int tid = threadIdx.x;
    int lane = tid & 31, wid = tid >> 5;
    int base = tid * vpt;
    int vals[16];
    int s = 0;
    #pragma unroll
    for (int i = 0; i < 16; i++) {
        if (i < vpt) {
            int idx = base + i;
            vals[i] = (idx < N) ? g_deg[b][idx] : 0;
            s += vals[i];
        }
    }
    // block scan of per-thread sums
    int sc = s;
    #pragma unroll
    for (int off = 1; off < 32; off <<= 1) {
        int t = __shfl_up_sync(0xFFFFFFFF, sc, off);
        if (lane >= off) sc += t;
    }
    if (lane == 31) wsum[wid] = sc;
    __syncthreads();
    if (wid == 0) {
        int ws = wsum[lane];
        #pragma unroll
        for (int off = 1; off < 32; off <<= 1) {
            int t = __shfl_up_sync(0xFFFFFFFF, ws, off);
            if (lane >= off) ws += t;
        }
        wsum[lane] = ws;
    }
    __syncthreads();
    int run = sc - s + (wid > 0 ? wsum[wid - 1] : 0);   // exclusive offset
    #pragma unroll
    for (int i = 0; i < 16; i++) {
        if (i < vpt) {
            int idx = base + i;
            if (idx < N) {
                g_rowptr[b][idx] = run;
                g_cursor[b][idx] = run;
                run += vals[i];
            }
        }
    }
    if (tid == 1023) g_rowptr[b][N] = run;
    for (int i = tid; i < N; i += 1024)
        g_dinv[b][i] = rsqrtf((float)(g_deg[b][i] + 1));
}

// ---------------- per-branch x->fp16 convert + W transpose ----------------
__global__ __launch_bounds__(1024)
void k_cvt1(const float* __restrict__ x, const float* __restrict__ W,
            int b, int cvb, int total4) {
    __shared__ float smem_t[4][32][33];
    int bx = blockIdx.x;
    int tid = threadIdx.x;
    if ((int)bx < cvb) {
        long long li = (long long)bx * 1024 + tid;
        if (li < total4) {
            const float4* __restrict__ x4 = (const float4*)x;
            float4 v = __ldg(&x4[li]);
            __half2 h0 = __floats2half2_rn(v.x, v.y);
            __half2 h1 = __floats2half2_rn(v.z, v.w);
            uint2 u;
            u.x = *(uint32_t*)&h0; u.y = *(uint32_t*)&h1;
            ((uint2*)g_x16[b])[li] = u;
        }
    } else {
        int q = tid >> 8;
        int qt = tid & 255;
        int tileid = (bx - cvb) * 4 + q;      // 0..1023
        if (tileid < 1024) {
            int bxt = tileid & 31;
            int byt = tileid >> 5;
            int tx = qt & 31, ty = qt >> 5;
            int xg = bxt * 32 + tx;
            #pragma unroll
            for (int j = 0; j < 4; j++) {
                int y = byt * 32 + ty + j * 8;
                smem_t[q][ty + j * 8][tx] = W[(size_t)y * F + xg];
            }
            __syncthreads();
            int xo = byt * 32 + tx;
            #pragma unroll
            for (int j = 0; j < 4; j++) {
                int yo = bxt * 32 + ty + j * 8;
                g_wh[b][(size_t)yo * F + xo] = __float2half_rn(smem_t[q][tx][ty + j * 8]);
            }
        }
    }
}

// ---------------- per-branch CSR fill (4 edges/thread) ----------------
__global__ void k_fill1(const void* __restrict__ ei, int E, int b, int slot) {
    int is64 = g_is64[slot];
    int e = (blockIdx.x * blockDim.x + threadIdx.x) * 4;
    if (e + 4 <= E) {
        int s0 = idx_at(ei, e + 0, is64), d0 = idx_at(ei, (long long)E + e + 0, is64);
        int s1 = idx_at(ei, e + 1, is64), d1 = idx_at(ei, (long long)E + e + 1, is64);
        int s2 = idx_at(ei, e + 2, is64), d2 = idx_at(ei, (long long)E + e + 2, is64);
        int s3 = idx_at(ei, e + 3, is64), d3 = idx_at(ei, (long long)E + e + 3, is64);
        int p0 = atomicAdd(&g_cursor[b][d0], 1);
        int p1 = atomicAdd(&g_cursor[b][d1], 1);
        int p2 = atomicAdd(&g_cursor[b][d2], 1);
        int p3 = atomicAdd(&g_cursor[b][d3], 1);
        g_col[b][p0] = s0;
        g_col[b][p1] = s1;
        g_col[b][p2] = s2;
        g_col[b][p3] = s3;
    } else {
        for (int i = e; i < E; i++) {
            int s = idx_at(ei, i, is64);
            int d = idx_at(ei, (long long)E + i, is64);
            int pos = atomicAdd(&g_cursor[b][d], 1);
            g_col[b][pos] = s;
        }
    }
}

// ---------------- per-branch aggregation over row range [roff, roff+cnt) ----------------
__global__ void k_agg1(int b, int roff) {
    int row = roff + blockIdx.x;
    int t = threadIdx.x;
    const uint2* __restrict__ x2v = (const uint2*)g_x16[b];
    const int* __restrict__ col = g_col[b];
    const float* __restrict__ dinv = g_dinv[b];
    float dv = dinv[row];
    uint2 xr = __ldg(&x2v[(size_t)row * 256 + t]);
    __half2 xr0 = *(__half2*)&xr.x, xr1 = *(__half2*)&xr.y;
    float w0 = dv * dv;
    float2 f0 = __half22float2(xr0), f1 = __half22float2(xr1);
    float4 acc;
    acc.x = f0.x * w0; acc.y = f0.y * w0; acc.z = f1.x * w0; acc.w = f1.y * w0;
    int s = g_rowptr[b][row], e = g_rowptr[b][row + 1];
    int j = s;
    for (; j + 4 <= e; j += 4) {
        int u0 = col[j], u1 = col[j + 1], u2 = col[j + 2], u3 = col[j + 3];
        float wa = dinv[u0] * dv, wb = dinv[u1] * dv;
        float wc = dinv[u2] * dv, wd = dinv[u3] * dv;
        uint2 v0 = __ldg(&x2v[(size_t)u0 * 256 + t]);
        uint2 v1 = __ldg(&x2v[(size_t)u1 * 256 + t]);
        uint2 v2 = __ldg(&x2v[(size_t)u2 * 256 + t]);
        uint2 v3 = __ldg(&x2v[(size_t)u3 * 256 + t]);
        float2 a0 = __half22float2(*(__half2*)&v0.x), a1 = __half22float2(*(__half2*)&v0.y);
        acc.x += a0.x * wa; acc.y += a0.y * wa; acc.z += a1.x * wa; acc.w += a1.y * wa;
        float2 b0 = __half22float2(*(__half2*)&v1.x), b1 = __half22float2(*(__half2*)&v1.y);
        acc.x += b0.x * wb; acc.y += b0.y * wb; acc.z += b1.x * wb; acc.w += b1.y * wb;
        float2 c0 = __half22float2(*(__half2*)&v2.x), c1 = __half22float2(*(__half2*)&v2.y);
        acc.x += c0.x * wc; acc.y += c0.y * wc; acc.z += c1.x * wc; acc.w += c1.y * wc;
        float2 d0 = __half22float2(*(__half2*)&v3.x), d1 = __half22float2(*(__half2*)&v3.y);
        acc.x += d0.x * wd; acc.y += d0.y * wd; acc.z += d1.x * wd; acc.w += d1.y * wd;
    }
    for (; j < e; j++) {
        int u = col[j];
        float w = dinv[u] * dv;
        uint2 xu = __ldg(&x2v[(size_t)u * 256 + t]);
        float2 g0 = __half22float2(*(__half2*)&xu.x), g1 = __half22float2(*(__half2*)&xu.y);
        acc.x += g0.x * w; acc.y += g0.y * w; acc.z += g1.x * w; acc.w += g1.y * w;
    }
    __half2 p0 = __floats2half2_rn(acc.x, acc.y);
    __half2 p1 = __floats2half2_rn(acc.z, acc.w);
    uint2 v;
    v.x = *(uint32_t*)&p0; v.y = *(uint32_t*)&p1;
    ((uint2*)g_a16[b])[(size_t)row * 256 + t] = v;
}

// ---------------- fp16 HMMA GEMM over M tile range ----------------
#define BK        64
#define NCHUNK    (F / BK)            // 16
#define ROWPAD    72                   // fp16 elems per smem row (64 data + 8 pad)
#define SA_BYTES  (128 * ROWPAD * 2)   // 18432 per tensor
#define STG_BYTES (2 * SA_BYTES)       // A, W
#define SM_TOT    (2 * STG_BYTES)      // 73728

__global__ __launch_bounds__(256, 2)
void k_tgemm(const float* __restrict__ bias, int M, int br, int mtoff) {
    extern __shared__ char smem[];
    uint32_t sb = smem_to_u32(smem);
    const __half* __restrict__ A  = g_a16[br];
    const __half* __restrict__ Wh = g_wh[br];

    int tid = threadIdx.x;
    int wid = tid >> 5, lane = tid & 31;
    int gid = lane >> 2, tig = lane & 3;
    int warp_m = wid & 1, warp_n = wid >> 1;
    int m0 = (mtoff + blockIdx.y) * 128;
    int n0 = blockIdx.x * 128;

    float acc[4][4][4];
    #pragma unroll
    for (int i = 0; i < 4; i++)
        #pragma unroll
        for (int j = 0; j < 4; j++)
            #pragma unroll
            for (int q = 0; q < 4; q++) acc[i][j][q] = 0.0f;

    auto load_chunk = [&](int c, int s) {
        uint32_t stg = sb + s * STG_BYTES;
        int k0 = c * BK;
        #pragma unroll
        for (int l = 0; l < 8; l++) {
            int idx = l * 256 + tid;
            int tsr = idx >> 10;          // 0 A, 1 W
            int rem = idx & 1023;
            int row = rem >> 3;
            int c16 = rem & 7;
            const __half* gsrc;
            bool pred = true;
            if (tsr == 0) {
                int grow = m0 + row;
                pred = grow < M;
                gsrc = A + (size_t)(pred ? grow : 0) * F + k0 + c16 * 8;
            } else {
                gsrc = Wh + (size_t)(n0 + row) * F + k0 + c16 * 8;
            }
            uint32_t sdst = stg + tsr * SA_BYTES + row * (ROWPAD * 2) + c16 * 16;
            cp_async16(sdst, gsrc, pred);
        }
        cp_commit();
    };

    load_chunk(0, 0);

    for (int c = 0; c < NCHUNK; c++) {
        int s = c & 1;
        if (c + 1 < NCHUNK) {
            load_chunk(c + 1, s ^ 1);
            cp_wait<1>();
        } else {
            cp_wait<0>();
        }
        __syncthreads();

        uint32_t sa  = sb + s * STG_BYTES;
        uint32_t sbh = sa + SA_BYTES;

        #pragma unroll
        for (int ks = 0; ks < 4; ks++) {
            int kb = ks * 16;
            uint32_t bh[4][2];
            #pragma unroll
            for (int nt = 0; nt < 4; nt++) {
                int n = warp_n * 32 + nt * 8 + gid;
                uint32_t o = n * (ROWPAD * 2) + (kb + tig * 2) * 2;
                bh[nt][0] = lds32(sbh + o);
                bh[nt][1] = lds32(sbh + o + 16);
            }
            #pragma unroll
            for (int mt = 0; mt < 4; mt++) {
                int r = warp_m * 64 + mt * 16 + gid;
                uint32_t o = r * (ROWPAD * 2) + (kb + tig * 2) * 2;
                uint32_t ah[4];
                ah[0] = lds32(sa + o);
                ah[1] = lds32(sa + o + 8 * (ROWPAD * 2));
                ah[2] = lds32(sa + o + 16);
                ah[3] = lds32(sa + o + 8 * (ROWPAD * 2) + 16);
                #pragma unroll
                for (int nt = 0; nt < 4; nt++) {
                    mma16816(acc[mt][nt], ah, bh[nt]);
                }
            }
        }
        __syncthreads();
    }

    __half* __restrict__ Y = g_y16[br];
    #pragma unroll
    for (int mt = 0; mt < 4; mt++) {
        int r0 = m0 + warp_m * 64 + mt * 16 + gid;
        #pragma unroll
        for (int nt = 0; nt < 4; nt++) {
            int col = n0 + warp_n * 32 + nt * 8 + tig * 2;
            float b0 = __ldg(&bias[col]);
            float b1 = __ldg(&bias[col + 1]);
            float* cf = acc[mt][nt];
            if (r0 < M) {
                __half2 v = __floats2half2_rn(leaky(cf[0] + b0), leaky(cf[1] + b1));
                *(__half2*)(Y + (size_t)r0 * F + col) = v;
            }
            if (r0 + 8 < M) {
                __half2 v = __floats2half2_rn(leaky(cf[2] + b0), leaky(cf[3] + b1));
                *(__half2*)(Y + (size_t)(r0 + 8) * F + col) = v;
            }
        }
    }
}

// ---------------- per-branch pool: one block per graph ----------------
__global__ __launch_bounds__(256)
void k_pool2(int b) {
    int g = blockIdx.x;
    int t = threadIdx.x;
    int s = g_goff[b][g], e = g_goff[b][g + 1];
    const __half2* __restrict__ Y2 = (const __half2*)g_y16[b];
    float2 s0 = {0.f, 0.f}, s1 = {0.f, 0.f};
    for (int r = s; r < e; r++) {
        float2 a = __half22float2(Y2[(size_t)r * 512 + t]);
        float2 c = __half22float2(Y2[(size_t)r * 512 + t + 256]);
        s0.x += a.x; s0.y += a.y; s1.x += c.x; s1.y += c.y;
    }
    float inv = 1.0f / fmaxf((float)(e - s), 1.0f);
    g_pool[b][g * F + 2 * t]             = s0.x * inv;
    g_pool[b][g * F + 2 * t + 1]         = s0.y * inv;
    g_pool[b][g * F + 2 * (t + 256)]     = s1.x * inv;
    g_pool[b][g * F + 2 * (t + 256) + 1] = s1.y * inv;
}

// ---------------- final: fc both branches + concat dot ----------------
__global__ __launch_bounds__(256)
void k_fin(const float* __restrict__ Wf0, const float* __restrict__ bf0,
           const float* __restrict__ Wf1, const float* __restrict__ bf1,
           const float* __restrict__ fW, const float* __restrict__ fb,
           float* __restrict__ out) {
    __shared__ float p[2 * F];
    __shared__ float zr[256];
    int g = blockIdx.x;
    int tid = threadIdx.x;
    for (int k = tid; k < 2 * F; k += 256) {
        int bb = k >> 10;
        p[k] = g_pool[bb][g * F + (k & 1023)];
    }
    __syncthreads();
    int bb = tid >> 7, col = tid & 127;
    const float* __restrict__ Wf = bb ? Wf1 : Wf0;
    const float* __restrict__ bf = bb ? bf1 : bf0;
    float acc = 0.0f;
    #pragma unroll 8
    for (int k = 0; k < F; k++) acc += p[bb * F + k] * Wf[k * DD + col];
    acc += bf[col];
    zr[tid] = leaky(acc) * fW[tid];
    __syncthreads();
    if (tid < 128) zr[tid] += zr[tid + 128];
    __syncthreads();
    if (tid < 64) zr[tid] += zr[tid + 64];
    __syncthreads();
    if (tid < 32) {
        float v = zr[tid] + zr[tid + 32];
        #pragma unroll
        for (int off = 16; off > 0; off >>= 1)
            v += __shfl_down_sync(0xFFFFFFFF, v, off);
        if (tid == 0) out[g] = v + fb[0];
    }
}

// ---------------- static streams/events for the pipelined graph ----------------
struct HxStreams {
    cudaStream_t q0 = 0, p1 = 0, q1 = 0;
    cudaEvent_t ePre = 0;
    cudaEvent_t eCvt[2] = {0, 0};
    cudaEvent_t eA0[2] = {0, 0}, eA1[2] = {0, 0};
    cudaEvent_t eG[2] = {0, 0};
    bool ok = false;
    HxStreams() {
        bool good = true;
        good &= cudaStreamCreateWithFlags(&q0, cudaStreamNonBlocking) == cudaSuccess;
        good &= cudaStreamCreateWithFlags(&p1, cudaStreamNonBlocking) == cudaSuccess;
        good &= cudaStreamCreateWithFlags(&q1, cudaStreamNonBlocking) == cudaSuccess;
        good &= cudaEventCreateWithFlags(&ePre, cudaEventDisableTiming) == cudaSuccess;
        for (int b = 0; b < 2; b++) {
            good &= cudaEventCreateWithFlags(&eCvt[b], cudaEventDisableTiming) == cudaSuccess;
            good &= cudaEventCreateWithFlags(&eA0[b], cudaEventDisableTiming) == cudaSuccess;
            good &= cudaEventCreateWithFlags(&eA1[b], cudaEventDisableTiming) == cudaSuccess;
            good &= cudaEventCreateWithFlags(&eG[b], cudaEventDisableTiming) == cudaSuccess;
        }
        ok = good;
    }
};
static HxStreams hx;

// ---------------- host launcher ----------------
extern "C" void kernel_launch(void* const* d_in, const int* in_sizes, int n_in,
                              void* d_out, int out_size) {
    const float* x1  = (const float*)d_in[0];
    const void*  ei1 = d_in[1];
    const void*  bt1 = d_in[2];
    const float* x2  = (const float*)d_in[3];
    const void*  ei2 = d_in[4];
    const void*  bt2 = d_in[5];
    int wb = n_in - 10;
    const float* c1W = (const float*)d_in[wb + 0];
    const float* c1b = (const float*)d_in[wb + 1];
    const float* f1W = (const float*)d_in[wb + 2];
    const float* f1b = (const float*)d_in[wb + 3];
    const float* c2W = (const float*)d_in[wb + 4];
    const float* c2b = (const float*)d_in[wb + 5];
    const float* f2W = (const float*)d_in[wb + 6];
    const float* f2b = (const float*)d_in[wb + 7];
    const float* fW  = (const float*)d_in[wb + 8];
    const float* fb  = (const float*)d_in[wb + 9];
    float* out = (float*)d_out;

    int N = in_sizes[0] / F;
    int E = in_sizes[1] / 2;

    const float* xs[2]  = {x1, x2};
    const void*  eis[2] = {ei1, ei2};
    const void*  bts[2] = {bt1, bt2};
    const float* cW[2]  = {c1W, c2W};
    const float* cb[2]  = {c1b, c2b};

    cudaFuncSetAttribute(k_tgemm, cudaFuncAttributeMaxDynamicSharedMemorySize, SM_TOT);

    int zb = (2 * MAXN + 255) / 256;
    int nbE4 = (E + 1023) / 1024;      // 4 edges/thread, 256 threads
    int total4 = N * (F / 4);
    int cvb = (total4 + 1023) / 1024;
    int vpt = (N + 1023) / 1024;
    if (vpt > 16) vpt = 16;            // capacity guard (N <= 16384)
    int mt = (N + 127) / 128;
    int mh0 = (mt + 1) / 2;
    int mh1 = mt - mh0;
    int rows0 = mh0 * 128; if (rows0 > N) rows0 = N;
    int rows1 = N - rows0;

    if (hx.ok) {
        cudaStream_t P[2] = {0, hx.p1};
        cudaStream_t Q[2] = {hx.q0, hx.q1};

        k_pre<<<4 + zb, 256>>>((const unsigned int*)ei1, (const unsigned int*)bt1,
                               (const unsigned int*)ei2, (const unsigned int*)bt2,
                               2 * E, N, 2 * E, N);
        cudaEventRecord(hx.ePre, 0);
        cudaStreamWaitEvent(hx.p1, hx.ePre, 0);
        cudaStreamWaitEvent(hx.q0, hx.ePre, 0);
        cudaStreamWaitEvent(hx.q1, hx.ePre, 0);

        for (int b = 0; b < 2; b++) {
            k_cvt1<<<cvb + 256, 1024, 0, Q[b]>>>(xs[b], cW[b], b, cvb, total4);
            cudaEventRecord(hx.eCvt[b], Q[b]);
        }

        for (int b = 0; b < 2; b++) {
            k_deg1<<<nbE4, 256, 0, P[b]>>>(eis[b], E, 2 * b, b);
            k_scan1<<<2, 1024, 0, P[b]>>>(N, b, bts[b], 2 * b + 1, vpt);
            k_fill1<<<nbE4, 256, 0, P[b]>>>(eis[b], E, b, 2 * b);
            cudaStreamWaitEvent(P[b], hx.eCvt[b], 0);
            k_agg1<<<rows0, 256, 0, P[b]>>>(b, 0);
            cudaEventRecord(hx.eA0[b], P[b]);
            if (rows1 > 0) {
                k_agg1<<<rows1, 256, 0, P[b]>>>(b, rows0);
            }
            cudaEventRecord(hx.eA1[b], P[b]);
            cudaStreamWaitEvent(Q[b], hx.eA0[b], 0);
            k_tgemm<<<dim3(F / 128, mh0), 256, SM_TOT, Q[b]>>>(cb[b], N, b, 0);
            if (mh1 > 0) {
                cudaStreamWaitEvent(Q[b], hx.eA1[b], 0);
                k_tgemm<<<dim3(F / 128, mh1), 256, SM_TOT, Q[b]>>>(cb[b], N, b, mh0);
            }
            k_pool2<<<NG, 256, 0, Q[b]>>>(b);
            cudaEventRecord(hx.eG[b], Q[b]);
        }
        cudaStreamWaitEvent(0, hx.eA1[1], 0);
        cudaStreamWaitEvent(0, hx.eG[0], 0);
        cudaStreamWaitEvent(0, hx.eG[1], 0);
        k_fin<<<NG, 256>>>(f1W, f1b, f2W, f2b, fW, fb, out);
    } else {
        k_pre<<<4 + zb, 256>>>((const unsigned int*)ei1, (const unsigned int*)bt1,
                               (const unsigned int*)ei2, (const unsigned int*)bt2,
                               2 * E, N, 2 * E, N);
        for (int b = 0; b < 2; b++) {
            k_cvt1<<<cvb + 256, 1024>>>(xs[b], cW[b], b, cvb, total4);
            k_deg1<<<nbE4, 256>>>(eis[b], E, 2 * b, b);
            k_scan1<<<2, 1024>>>(N, b, bts[b], 2 * b + 1, vpt);
            k_fill1<<<nbE4, 256>>>(eis[b], E, b, 2 * b);
            k_agg1<<<N, 256>>>(b, 0);
            k_tgemm<<<dim3(F / 128, mt), 256, SM_TOT>>>(cb[b], N, b, 0);
            k_pool2<<<NG, 256>>>(b);
        }
        k_fin<<<NG, 256>>>(f1W, f1b, f2W, f2b, fW, fb, out);
    }
}

// round 16
// speedup vs baseline: 1.0065x; 1.0065x over previous
#include <cuda_runtime.h>
#include <cuda_fp16.h>
#include <cstdint>
#include <math.h>

#define F    1024
#define MAXN 10000
#define MAXE 80000
#define NG   64
#define DD   128

// ---------------- static device scratch ----------------
__device__ __half g_x16[2][(size_t)MAXN * F];    // fp16(x)
__device__ __half g_y16[2][(size_t)MAXN * F];    // fp16(leaky(agg@W + b))
__device__ __half g_a16[2][(size_t)MAXN * F];    // fp16(agg)
__device__ __half g_wh[2][(size_t)F * F];        // fp16(W^T)  [n][k]
__device__ int   g_deg[2][MAXN];
__device__ float g_dinv[2][MAXN];
__device__ int   g_rowptr[2][MAXN + 1];
__device__ int   g_cursor[2][MAXN];
__device__ int   g_col[2][MAXE];
__device__ int   g_goff[2][NG + 1];
__device__ int   g_is64[4];   // 0: edge b0, 1: batch b0, 2: edge b1, 3: batch b1

__device__ __forceinline__ float leaky(float v) { return v >= 0.0f ? v : 0.01f * v; }

__device__ __forceinline__ int idx_at(const void* p, long long i, int is64) {
    return is64 ? (int)(((const long long*)p)[i]) : ((const int*)p)[i];
}

// ---------------- low-level helpers ----------------
__device__ __forceinline__ uint32_t smem_to_u32(const void* smem_ptr) {
    uint32_t addr;
    asm("{ .reg .u64 tmp; cvta.to.shared.u64 tmp, %1; cvt.u32.u64 %0, tmp; }"
        : "=r"(addr) : "l"(smem_ptr));
    return addr;
}
__device__ __forceinline__ void cp_async16(uint32_t dst, const void* src, bool p) {
    asm volatile("cp.async.cg.shared.global [%0], [%1], 16, %2;"
                 :: "r"(dst), "l"(src), "r"(p ? 16u : 0u) : "memory");
}
__device__ __forceinline__ void cp_commit() {
    asm volatile("cp.async.commit_group;" ::: "memory");
}
template <int N>
__device__ __forceinline__ void cp_wait() {
    asm volatile("cp.async.wait_group %0;" :: "n"(N) : "memory");
}
__device__ __forceinline__ uint32_t lds32(uint32_t addr) {
    uint32_t v;
    asm volatile("ld.shared.b32 %0, [%1];" : "=r"(v) : "r"(addr));
    return v;
}
__device__ __forceinline__ void mma16816(float* c, const uint32_t* a, const uint32_t* b) {
    asm volatile(
        "mma.sync.aligned.m16n8k16.row.col.f32.f16.f16.f32 "
        "{%0,%1,%2,%3}, {%4,%5,%6,%7}, {%8,%9}, {%0,%1,%2,%3};"
        : "+f"(c[0]), "+f"(c[1]), "+f"(c[2]), "+f"(c[3])
        : "r"(a[0]), "r"(a[1]), "r"(a[2]), "r"(a[3]), "r"(b[0]), "r"(b[1]));
}

// ---------------- k_pre: dtype detect (tail-scan) + deg zeroing ----------------
__global__ void k_pre(const unsigned int* p0, const unsigned int* p1,
                      const unsigned int* p2, const unsigned int* p3,
                      int nw0, int nw1, int nw2, int nw3) {
    if (blockIdx.x < 4) {
        const unsigned int* p; int nw;
        if (blockIdx.x == 0)      { p = p0; nw = nw0; }
        else if (blockIdx.x == 1) { p = p1; nw = nw1; }
        else if (blockIdx.x == 2) { p = p2; nw = nw2; }
        else                      { p = p3; nw = nw3; }
        int start = nw > 4096 ? nw - 4096 : 0;
        __shared__ unsigned int sh[256];
        unsigned int acc = 0;
        for (int i = start + threadIdx.x; i < nw; i += 256)
            if (i & 1) acc |= p[i];
        sh[threadIdx.x] = acc;
        __syncthreads();
        for (int s = 128; s > 0; s >>= 1) {
            if (threadIdx.x < s) sh[threadIdx.x] |= sh[threadIdx.x + s];
            __syncthreads();
        }
        if (threadIdx.x == 0) g_is64[blockIdx.x] = (sh[0] == 0u) ? 1 : 0;
    } else {
        int i = (blockIdx.x - 4) * 256 + threadIdx.x;
        if (i < 2 * MAXN) ((int*)g_deg)[i] = 0;
    }
}

// ---------------- per-branch degree histogram ----------------
__global__ void k_deg1(const void* __restrict__ ei, int E, int slot, int b) {
    int e = blockIdx.x * blockDim.x + threadIdx.x;
    if (e < E) {
        int is64 = g_is64[slot];
        atomicAdd(&g_deg[b][idx_at(ei, (long long)E + e, is64)], 1);
    }
}

// ---------------- per-branch single-pass scan (+dinv) and goff ----------------
__global__ __launch_bounds__(1024)
void k_scan1(int N, int b, const void* __restrict__ batch, int bslot, int vpt) {
    if (blockIdx.x == 1) {
        int g = threadIdx.x;
        if (g > NG) return;
        int is64 = g_is64[bslot];
        int lo = 0, hi = N;
        while (lo < hi) {
            int mid = (lo + hi) >> 1;
            if (idx_at(batch, mid, is64) < g) lo = mid + 1; else hi = mid;
        }
        g_goff[b][g] = lo;
        return;
    }
    __shared__ int wsum[32];
    int tid = threadIdx.x;
    int lane = tid & 31, wid = tid >> 5;
    int base = tid * vpt;
    int vals[16];
    int s = 0;
    #pragma unroll
    for (int i = 0; i < 16; i++) {
        if (i < vpt) {
            int idx = base + i;
            vals[i] = (idx < N) ? g_deg[b][idx] : 0;
            s += vals[i];
        }
    }
    // block scan of per-thread sums (2-level shuffle)
    int sc = s;
    #pragma unroll
    for (int off = 1; off < 32; off <<= 1) {
        int t = __shfl_up_sync(0xFFFFFFFF, sc, off);
        if (lane >= off) sc += t;
    }
    if (lane == 31) wsum[wid] = sc;
    __syncthreads();
    if (wid == 0) {
        int ws = wsum[lane];
        #pragma unroll
        for (int off = 1; off < 32; off <<= 1) {
            int t = __shfl_up_sync(0xFFFFFFFF, ws, off);
            if (lane >= off) ws += t;
        }
        wsum[lane] = ws;
    }
    __syncthreads();
    int run = sc - s + (wid > 0 ? wsum[wid - 1] : 0);   // exclusive offset
    #pragma unroll
    for (int i = 0; i < 16; i++) {
        if (i < vpt) {
            int idx = base + i;
            if (idx < N) {
                g_rowptr[b][idx] = run;
                g_cursor[b][idx] = run;
                run += vals[i];
            }
        }
    }
    if (tid == 1023) g_rowptr[b][N] = run;
    for (int i = tid; i < N; i += 1024)
        g_dinv[b][i] = rsqrtf((float)(g_deg[b][i] + 1));
}

// ---------------- per-branch x->fp16 convert + W transpose ----------------
__global__ __launch_bounds__(1024)
void k_cvt1(const float* __restrict__ x, const float* __restrict__ W,
            int b, int cvb, int total4) {
    __shared__ float smem_t[4][32][33];
    int bx = blockIdx.x;
    int tid = threadIdx.x;
    if ((int)bx < cvb) {
        long long li = (long long)bx * 1024 + tid;
        if (li < total4) {
            const float4* __restrict__ x4 = (const float4*)x;
            float4 v = __ldg(&x4[li]);
            __half2 h0 = __floats2half2_rn(v.x, v.y);
            __half2 h1 = __floats2half2_rn(v.z, v.w);
            uint2 u;
            u.x = *(uint32_t*)&h0; u.y = *(uint32_t*)&h1;
            ((uint2*)g_x16[b])[li] = u;
        }
    } else {
        int q = tid >> 8;
        int qt = tid & 255;
        int tileid = (bx - cvb) * 4 + q;      // 0..1023
        if (tileid < 1024) {
            int bxt = tileid & 31;
            int byt = tileid >> 5;
            int tx = qt & 31, ty = qt >> 5;
            int xg = bxt * 32 + tx;
            #pragma unroll
            for (int j = 0; j < 4; j++) {
                int y = byt * 32 + ty + j * 8;
                smem_t[q][ty + j * 8][tx] = W[(size_t)y * F + xg];
            }
            __syncthreads();
            int xo = byt * 32 + tx;
            #pragma unroll
            for (int j = 0; j < 4; j++) {
                int yo = bxt * 32 + ty + j * 8;
                g_wh[b][(size_t)yo * F + xo] = __float2half_rn(smem_t[q][tx][ty + j * 8]);
            }
        }
    }
}

// ---------------- per-branch CSR fill ----------------
__global__ void k_fill1(const void* __restrict__ ei, int E, int b, int slot) {
    int e = blockIdx.x * blockDim.x + threadIdx.x;
    if (e < E) {
        int is64 = g_is64[slot];
        int s = idx_at(ei, e, is64);
        int d = idx_at(ei, (long long)E + e, is64);
        int pos = atomicAdd(&g_cursor[b][d], 1);
        g_col[b][pos] = s;
    }
}

// ---------------- per-branch aggregation over row range [roff, roff+cnt) ----------------
__global__ void k_agg1(int b, int roff) {
    int row = roff + blockIdx.x;
    int t = threadIdx.x;
    const uint2* __restrict__ x2v = (const uint2*)g_x16[b];
    const int* __restrict__ col = g_col[b];
    const float* __restrict__ dinv = g_dinv[b];
    float dv = dinv[row];
    uint2 xr = __ldg(&x2v[(size_t)row * 256 + t]);
    __half2 xr0 = *(__half2*)&xr.x, xr1 = *(__half2*)&xr.y;
    float w0 = dv * dv;
    float2 f0 = __half22float2(xr0), f1 = __half22float2(xr1);
    float4 acc;
    acc.x = f0.x * w0; acc.y = f0.y * w0; acc.z = f1.x * w0; acc.w = f1.y * w0;
    int s = g_rowptr[b][row], e = g_rowptr[b][row + 1];
    int j = s;
    for (; j + 4 <= e; j += 4) {
        int u0 = col[j], u1 = col[j + 1], u2 = col[j + 2], u3 = col[j + 3];
        float wa = dinv[u0] * dv, wb = dinv[u1] * dv;
        float wc = dinv[u2] * dv, wd = dinv[u3] * dv;
        uint2 v0 = __ldg(&x2v[(size_t)u0 * 256 + t]);
        uint2 v1 = __ldg(&x2v[(size_t)u1 * 256 + t]);
        uint2 v2 = __ldg(&x2v[(size_t)u2 * 256 + t]);
        uint2 v3 = __ldg(&x2v[(size_t)u3 * 256 + t]);
        float2 a0 = __half22float2(*(__half2*)&v0.x), a1 = __half22float2(*(__half2*)&v0.y);
        acc.x += a0.x * wa; acc.y += a0.y * wa; acc.z += a1.x * wa; acc.w += a1.y * wa;
        float2 b0 = __half22float2(*(__half2*)&v1.x), b1 = __half22float2(*(__half2*)&v1.y);
        acc.x += b0.x * wb; acc.y += b0.y * wb; acc.z += b1.x * wb; acc.w += b1.y * wb;
        float2 c0 = __half22float2(*(__half2*)&v2.x), c1 = __half22float2(*(__half2*)&v2.y);
        acc.x += c0.x * wc; acc.y += c0.y * wc; acc.z += c1.x * wc; acc.w += c1.y * wc;
        float2 d0 = __half22float2(*(__half2*)&v3.x), d1 = __half22float2(*(__half2*)&v3.y);
        acc.x += d0.x * wd; acc.y += d0.y * wd; acc.z += d1.x * wd; acc.w += d1.y * wd;
    }
    for (; j < e; j++) {
        int u = col[j];
        float w = dinv[u] * dv;
        uint2 xu = __ldg(&x2v[(size_t)u * 256 + t]);
        float2 g0 = __half22float2(*(__half2*)&xu.x), g1 = __half22float2(*(__half2*)&xu.y);
        acc.x += g0.x * w; acc.y += g0.y * w; acc.z += g1.x * w; acc.w += g1.y * w;
    }
    __half2 p0 = __floats2half2_rn(acc.x, acc.y);
    __half2 p1 = __floats2half2_rn(acc.z, acc.w);
    uint2 v;
    v.x = *(uint32_t*)&p0; v.y = *(uint32_t*)&p1;
    ((uint2*)g_a16[b])[(size_t)row * 256 + t] = v;
}

// ---------------- fp16 HMMA GEMM over M tile range ----------------
#define BK        64
#define NCHUNK    (F / BK)            // 16
#define ROWPAD    72                   // fp16 elems per smem row (64 data + 8 pad)
#define SA_BYTES  (128 * ROWPAD * 2)   // 18432 per tensor
#define STG_BYTES (2 * SA_BYTES)       // A, W
#define SM_TOT    (2 * STG_BYTES)      // 73728

__global__ __launch_bounds__(256, 2)
void k_tgemm(const float* __restrict__ bias, int M, int br, int mtoff) {
    extern __shared__ char smem[];
    uint32_t sb = smem_to_u32(smem);
    const __half* __restrict__ A  = g_a16[br];
    const __half* __restrict__ Wh = g_wh[br];

    int tid = threadIdx.x;
    int wid = tid >> 5, lane = tid & 31;
    int gid = lane >> 2, tig = lane & 3;
    int warp_m = wid & 1, warp_n = wid >> 1;
    int m0 = (mtoff + blockIdx.y) * 128;
    int n0 = blockIdx.x * 128;

    float acc[4][4][4];
    #pragma unroll
    for (int i = 0; i < 4; i++)
        #pragma unroll
        for (int j = 0; j < 4; j++)
            #pragma unroll
            for (int q = 0; q < 4; q++) acc[i][j][q] = 0.0f;

    auto load_chunk = [&](int c, int s) {
        uint32_t stg = sb + s * STG_BYTES;
        int k0 = c * BK;
        #pragma unroll
        for (int l = 0; l < 8; l++) {
            int idx = l * 256 + tid;
            int tsr = idx >> 10;          // 0 A, 1 W
            int rem = idx & 1023;
            int row = rem >> 3;
            int c16 = rem & 7;
            const __half* gsrc;
            bool pred = true;
            if (tsr == 0) {
                int grow = m0 + row;
                pred = grow < M;
                gsrc = A + (size_t)(pred ? grow : 0) * F + k0 + c16 * 8;
            } else {
                gsrc = Wh + (size_t)(n0 + row) * F + k0 + c16 * 8;
            }
            uint32_t sdst = stg + tsr * SA_BYTES + row * (ROWPAD * 2) + c16 * 16;
            cp_async16(sdst, gsrc, pred);
        }
        cp_commit();
    };

    load_chunk(0, 0);

    for (int c = 0; c < NCHUNK; c++) {
        int s = c & 1;
        if (c + 1 < NCHUNK) {
            load_chunk(c + 1, s ^ 1);
            cp_wait<1>();
        } else {
            cp_wait<0>();
        }
        __syncthreads();

        uint32_t sa  = sb + s * STG_BYTES;
        uint32_t sbh = sa + SA_BYTES;

        #pragma unroll
        for (int ks = 0; ks < 4; ks++) {
            int kb = ks * 16;
            uint32_t bh[4][2];
            #pragma unroll
            for (int nt = 0; nt < 4; nt++) {
                int n = warp_n * 32 + nt * 8 + gid;
                uint32_t o = n * (ROWPAD * 2) + (kb + tig * 2) * 2;
                bh[nt][0] = lds32(sbh + o);
                bh[nt][1] = lds32(sbh + o + 16);
            }
            #pragma unroll
            for (int mt = 0; mt < 4; mt++) {
                int r = warp_m * 64 + mt * 16 + gid;
                uint32_t o = r * (ROWPAD * 2) + (kb + tig * 2) * 2;
                uint32_t ah[4];
                ah[0] = lds32(sa + o);
                ah[1] = lds32(sa + o + 8 * (ROWPAD * 2));
                ah[2] = lds32(sa + o + 16);
                ah[3] = lds32(sa + o + 8 * (ROWPAD * 2) + 16);
                #pragma unroll
                for (int nt = 0; nt < 4; nt++) {
                    mma16816(acc[mt][nt], ah, bh[nt]);
                }
            }
        }
        __syncthreads();
    }

    __half* __restrict__ Y = g_y16[br];
    #pragma unroll
    for (int mt = 0; mt < 4; mt++) {
        int r0 = m0 + warp_m * 64 + mt * 16 + gid;
        #pragma unroll
        for (int nt = 0; nt < 4; nt++) {
            int col = n0 + warp_n * 32 + nt * 8 + tig * 2;
            float b0 = __ldg(&bias[col]);
            float b1 = __ldg(&bias[col + 1]);
            float* cf = acc[mt][nt];
            if (r0 < M) {
                __half2 v = __floats2half2_rn(leaky(cf[0] + b0), leaky(cf[1] + b1));
                *(__half2*)(Y + (size_t)r0 * F + col) = v;
            }
            if (r0 + 8 < M) {
                __half2 v = __floats2half2_rn(leaky(cf[2] + b0), leaky(cf[3] + b1));
                *(__half2*)(Y + (size_t)(r0 + 8) * F + col) = v;
            }
        }
    }
}

// ---------------- fused tail: pool + fc + final, one block per graph ----------------
__global__ __launch_bounds__(512)
void k_tail(const float* __restrict__ Wf0, const float* __restrict__ bf0,
            const float* __restrict__ Wf1, const float* __restrict__ bf1,
            const float* __restrict__ fW, const float* __restrict__ fb,
            float* __restrict__ out) {
    __shared__ float p[2][F];
    __shared__ float zr[256];
    int g = blockIdx.x;
    int tid = threadIdx.x;
    int b = tid >> 8, t = tid & 255;

    int s = g_goff[b][g], e = g_goff[b][g + 1];
    const __half2* __restrict__ Y2 = (const __half2*)g_y16[b];
    float2 s0 = {0.f, 0.f}, s1 = {0.f, 0.f};
    for (int r = s; r < e; r++) {
        float2 a = __half22float2(Y2[(size_t)r * 512 + t]);
        float2 c = __half22float2(Y2[(size_t)r * 512 + t + 256]);
        s0.x += a.x; s0.y += a.y; s1.x += c.x; s1.y += c.y;
    }
    float inv = 1.0f / fmaxf((float)(e - s), 1.0f);
    p[b][2 * t]             = s0.x * inv;
    p[b][2 * t + 1]         = s0.y * inv;
    p[b][2 * (t + 256)]     = s1.x * inv;
    p[b][2 * (t + 256) + 1] = s1.y * inv;
    __syncthreads();

    if (tid < 256) {
        int bb = tid >> 7, col = tid & 127;
        const float* __restrict__ Wf = bb ? Wf1 : Wf0;
        const float* __restrict__ bf = bb ? bf1 : bf0;
        float acc = 0.0f;
        #pragma unroll 8
        for (int k = 0; k < F; k++) acc += p[bb][k] * Wf[k * DD + col];
        acc += bf[col];
        zr[tid] = leaky(acc) * fW[tid];
    }
    __syncthreads();

    if (tid < 128) zr[tid] += zr[tid + 128];
    __syncthreads();
    if (tid < 64) zr[tid] += zr[tid + 64];
    __syncthreads();
    if (tid < 32) {
        float v = zr[tid] + zr[tid + 32];
        #pragma unroll
        for (int off = 16; off > 0; off >>= 1)
            v += __shfl_down_sync(0xFFFFFFFF, v, off);
        if (tid == 0) out[g] = v + fb[0];
    }
}

// ---------------- static streams/events for the pipelined graph ----------------
struct HxStreams {
    cudaStream_t q0 = 0, p1 = 0, q1 = 0;
    cudaEvent_t ePre = 0;
    cudaEvent_t eCvt[2] = {0, 0};
    cudaEvent_t eA0[2] = {0, 0}, eA1[2] = {0, 0};
    cudaEvent_t eG[2] = {0, 0};
    bool ok = false;
    HxStreams() {
        bool good = true;
        good &= cudaStreamCreateWithFlags(&q0, cudaStreamNonBlocking) == cudaSuccess;
        good &= cudaStreamCreateWithFlags(&p1, cudaStreamNonBlocking) == cudaSuccess;
        good &= cudaStreamCreateWithFlags(&q1, cudaStreamNonBlocking) == cudaSuccess;
        good &= cudaEventCreateWithFlags(&ePre, cudaEventDisableTiming) == cudaSuccess;
        for (int b = 0; b < 2; b++) {
            good &= cudaEventCreateWithFlags(&eCvt[b], cudaEventDisableTiming) == cudaSuccess;
            good &= cudaEventCreateWithFlags(&eA0[b], cudaEventDisableTiming) == cudaSuccess;
            good &= cudaEventCreateWithFlags(&eA1[b], cudaEventDisableTiming) == cudaSuccess;
            good &= cudaEventCreateWithFlags(&eG[b], cudaEventDisableTiming) == cudaSuccess;
        }
        ok = good;
    }
};
static HxStreams hx;

// ---------------- host launcher ----------------
extern "C" void kernel_launch(void* const* d_in, const int* in_sizes, int n_in,
                              void* d_out, int out_size) {
    const float* x1  = (const float*)d_in[0];
    const void*  ei1 = d_in[1];
    const void*  bt1 = d_in[2];
    const float* x2  = (const float*)d_in[3];
    const void*  ei2 = d_in[4];
    const void*  bt2 = d_in[5];
    int wb = n_in - 10;
    const float* c1W = (const float*)d_in[wb + 0];
    const float* c1b = (const float*)d_in[wb + 1];
    const float* f1W = (const float*)d_in[wb + 2];
    const float* f1b = (const float*)d_in[wb + 3];
    const float* c2W = (const float*)d_in[wb + 4];
    const float* c2b = (const float*)d_in[wb + 5];
    const float* f2W = (const float*)d_in[wb + 6];
    const float* f2b = (const float*)d_in[wb + 7];
    const float* fW  = (const float*)d_in[wb + 8];
    const float* fb  = (const float*)d_in[wb + 9];
    float* out = (float*)d_out;

    int N = in_sizes[0] / F;
    int E = in_sizes[1] / 2;

    const float* xs[2]  = {x1, x2};
    const void*  eis[2] = {ei1, ei2};
    const void*  bts[2] = {bt1, bt2};
    const float* cW[2]  = {c1W, c2W};
    const float* cb[2]  = {c1b, c2b};

    cudaFuncSetAttribute(k_tgemm, cudaFuncAttributeMaxDynamicSharedMemorySize, SM_TOT);

    int zb = (2 * MAXN + 255) / 256;
    int nbE = (E + 255) / 256;
    int total4 = N * (F / 4);
    int cvb = (total4 + 1023) / 1024;
    int vpt = (N + 1023) / 1024;
    if (vpt > 16) vpt = 16;            // capacity guard (N <= 16384)
    int mt = (N + 127) / 128;
    int mh0 = (mt + 1) / 2;
    int mh1 = mt - mh0;
    int rows0 = mh0 * 128; if (rows0 > N) rows0 = N;
    int rows1 = N - rows0;

    if (hx.ok) {
        cudaStream_t P[2] = {0, hx.p1};
        cudaStream_t Q[2] = {hx.q0, hx.q1};

        // pre on the capture-origin stream, then FORK all side streams from it
        k_pre<<<4 + zb, 256>>>((const unsigned int*)ei1, (const unsigned int*)bt1,
                               (const unsigned int*)ei2, (const unsigned int*)bt2,
                               2 * E, N, 2 * E, N);
        cudaEventRecord(hx.ePre, 0);
        cudaStreamWaitEvent(hx.p1, hx.ePre, 0);
        cudaStreamWaitEvent(hx.q0, hx.ePre, 0);
        cudaStreamWaitEvent(hx.q1, hx.ePre, 0);

        // helpers: cvt (overlaps deg/scan/fill on primaries)
        for (int b = 0; b < 2; b++) {
            k_cvt1<<<cvb + 256, 1024, 0, Q[b]>>>(xs[b], cW[b], b, cvb, total4);
            cudaEventRecord(hx.eCvt[b], Q[b]);
        }

        for (int b = 0; b < 2; b++) {
            k_deg1<<<nbE, 256, 0, P[b]>>>(eis[b], E, 2 * b, b);
            k_scan1<<<2, 1024, 0, P[b]>>>(N, b, bts[b], 2 * b + 1, vpt);
            k_fill1<<<nbE, 256, 0, P[b]>>>(eis[b], E, b, 2 * b);
            cudaStreamWaitEvent(P[b], hx.eCvt[b], 0);
            k_agg1<<<rows0, 256, 0, P[b]>>>(b, 0);
            cudaEventRecord(hx.eA0[b], P[b]);
            if (rows1 > 0) {
                k_agg1<<<rows1, 256, 0, P[b]>>>(b, rows0);
            }
            cudaEventRecord(hx.eA1[b], P[b]);
            cudaStreamWaitEvent(Q[b], hx.eA0[b], 0);
            k_tgemm<<<dim3(F / 128, mh0), 256, SM_TOT, Q[b]>>>(cb[b], N, b, 0);
            if (mh1 > 0) {
                cudaStreamWaitEvent(Q[b], hx.eA1[b], 0);
                k_tgemm<<<dim3(F / 128, mh1), 256, SM_TOT, Q[b]>>>(cb[b], N, b, mh0);
            }
            cudaEventRecord(hx.eG[b], Q[b]);
        }
        cudaStreamWaitEvent(0, hx.eA1[1], 0);
        cudaStreamWaitEvent(0, hx.eG[0], 0);
        cudaStreamWaitEvent(0, hx.eG[1], 0);
        k_tail<<<NG, 512>>>(f1W, f1b, f2W, f2b, fW, fb, out);
    } else {
        // fallback: sequential on legacy stream
        k_pre<<<4 + zb, 256>>>((const unsigned int*)ei1, (const unsigned int*)bt1,
                               (const unsigned int*)ei2, (const unsigned int*)bt2,
                               2 * E, N, 2 * E, N);
        for (int b = 0; b < 2; b++) {
            k_cvt1<<<cvb + 256, 1024>>>(xs[b], cW[b], b, cvb, total4);
            k_deg1<<<nbE, 256>>>(eis[b], E, 2 * b, b);
            k_scan1<<<2, 1024>>>(N, b, bts[b], 2 * b + 1, vpt);
            k_fill1<<<nbE, 256>>>(eis[b], E, b, 2 * b);
            k_agg1<<<N, 256>>>(b, 0);
            k_tgemm<<<dim3(F / 128, mt), 256, SM_TOT>>>(cb[b], N, b, 0);
        }
        k_tail<<<NG, 512>>>(f1W, f1b, f2W, f2b, fW, fb, out);
    }
}

// round 17
// speedup vs baseline: 1.0304x; 1.0237x over previous
#include <cuda_runtime.h>
#include <cuda_fp16.h>
#include <cstdint>
#include <math.h>

#define F    1024
#define MAXN 10000
#define MAXE 80000
#define NG   64
#define DD   128

// ---------------- static device scratch ----------------
__device__ __half g_x16[2][(size_t)MAXN * F];    // fp16(x)
__device__ __half g_y16[2][(size_t)MAXN * F];    // fp16(leaky(agg@W + b))
__device__ __half g_a16[2][(size_t)MAXN * F];    // fp16(agg)
__device__ __half g_wh[2][(size_t)F * F];        // fp16(W^T)  [n][k]
__device__ int   g_deg[2][MAXN];                 // zero at load; re-zeroed by k_agg1 each call
__device__ float g_dinv[2][MAXN];
__device__ int   g_rowptr[2][MAXN + 1];
__device__ int   g_cursor[2][MAXN];
__device__ int   g_col[2][MAXE];
__device__ int   g_goff[2][NG + 1];
__device__ int   g_is64[4];   // 0: edge b0, 1: batch b0, 2: edge b1, 3: batch b1

__device__ __forceinline__ float leaky(float v) { return v >= 0.0f ? v : 0.01f * v; }

__device__ __forceinline__ int idx_at(const void* p, long long i, int is64) {
    return is64 ? (int)(((const long long*)p)[i]) : ((const int*)p)[i];
}

// ---------------- low-level helpers ----------------
__device__ __forceinline__ uint32_t smem_to_u32(const void* smem_ptr) {
    uint32_t addr;
    asm("{ .reg .u64 tmp; cvta.to.shared.u64 tmp, %1; cvt.u32.u64 %0, tmp; }"
        : "=r"(addr) : "l"(smem_ptr));
    return addr;
}
__device__ __forceinline__ void cp_async16(uint32_t dst, const void* src, bool p) {
    asm volatile("cp.async.cg.shared.global [%0], [%1], 16, %2;"
                 :: "r"(dst), "l"(src), "r"(p ? 16u : 0u) : "memory");
}
__device__ __forceinline__ void cp_commit() {
    asm volatile("cp.async.commit_group;" ::: "memory");
}
template <int N>
__device__ __forceinline__ void cp_wait() {
    asm volatile("cp.async.wait_group %0;" :: "n"(N) : "memory");
}
__device__ __forceinline__ uint32_t lds32(uint32_t addr) {
    uint32_t v;
    asm volatile("ld.shared.b32 %0, [%1];" : "=r"(v) : "r"(addr));
    return v;
}
__device__ __forceinline__ void mma16816(float* c, const uint32_t* a, const uint32_t* b) {
    asm volatile(
        "mma.sync.aligned.m16n8k16.row.col.f32.f16.f16.f32 "
        "{%0,%1,%2,%3}, {%4,%5,%6,%7}, {%8,%9}, {%0,%1,%2,%3};"
        : "+f"(c[0]), "+f"(c[1]), "+f"(c[2]), "+f"(c[3])
        : "r"(a[0]), "r"(a[1]), "r"(a[2]), "r"(a[3]), "r"(b[0]), "r"(b[1]));
}

// ---------------- k_pre: dtype detect ONLY (4 blocks) ----------------
__global__ void k_pre(const unsigned int* p0, const unsigned int* p1,
                      const unsigned int* p2, const unsigned int* p3,
                      int nw0, int nw1, int nw2, int nw3) {
    const unsigned int* p; int nw;
    if (blockIdx.x == 0)      { p = p0; nw = nw0; }
    else if (blockIdx.x == 1) { p = p1; nw = nw1; }
    else if (blockIdx.x == 2) { p = p2; nw = nw2; }
    else                      { p = p3; nw = nw3; }
    int start = nw > 4096 ? nw - 4096 : 0;
    __shared__ unsigned int sh[256];
    unsigned int acc = 0;
    for (int i = start + threadIdx.x; i < nw; i += 256)
        if (i & 1) acc |= p[i];
    sh[threadIdx.x] = acc;
    __syncthreads();
    for (int s = 128; s > 0; s >>= 1) {
        if (threadIdx.x < s) sh[threadIdx.x] |= sh[threadIdx.x + s];
        __syncthreads();
    }
    if (threadIdx.x == 0) g_is64[blockIdx.x] = (sh[0] == 0u) ? 1 : 0;
}

// ---------------- per-branch degree histogram ----------------
__global__ void k_deg1(const void* __restrict__ ei, int E, int slot, int b) {
    int e = blockIdx.x * blockDim.x + threadIdx.x;
    if (e < E) {
        int is64 = g_is64[slot];
        atomicAdd(&g_deg[b][idx_at(ei, (long long)E + e, is64)], 1);
    }
}

// ---------------- per-branch scan (multi-tile, coalesced + prefetch) and goff ----------------
__global__ __launch_bounds__(1024)
void k_scan1(int N, int b, const void* __restrict__ batch, int bslot) {
    if (blockIdx.x == 1) {
        int g = threadIdx.x;
        if (g > NG) return;
        int is64 = g_is64[bslot];
        int lo = 0, hi = N;
        while (lo < hi) {
            int mid = (lo + hi) >> 1;
            if (idx_at(batch, mid, is64) < g) lo = mid + 1; else hi = mid;
        }
        g_goff[b][g] = lo;
        return;
    }
    __shared__ int wsum[32];
    __shared__ int carry;
    int tid = threadIdx.x;
    int lane = tid & 31, wid = tid >> 5;
    if (tid == 0) carry = 0;
    int v_next = (tid < N) ? g_deg[b][tid] : 0;
    __syncthreads();
    for (int base = 0; base < N; base += 1024) {
        int v = v_next;
        int i2 = base + 1024 + tid;
        v_next = (i2 < N) ? g_deg[b][i2] : 0;
        int sc = v;
        #pragma unroll
        for (int off = 1; off < 32; off <<= 1) {
            int t = __shfl_up_sync(0xFFFFFFFF, sc, off);
            if (lane >= off) sc += t;
        }
        if (lane == 31) wsum[wid] = sc;
        __syncthreads();
        if (wid == 0) {
            int ws = wsum[lane];
            #pragma unroll
            for (int off = 1; off < 32; off <<= 1) {
                int t = __shfl_up_sync(0xFFFFFFFF, ws, off);
                if (lane >= off) ws += t;
            }
            wsum[lane] = ws;
        }
        __syncthreads();
        int incl = sc + (wid > 0 ? wsum[wid - 1] : 0) + carry;
        int i = base + tid;
        if (i < N) {
            g_rowptr[b][i] = incl - v;
            g_cursor[b][i] = incl - v;
        }
        __syncthreads();
        if (tid == 1023) carry = incl;
        __syncthreads();
    }
    if (tid == 0) g_rowptr[b][N] = carry;
    for (int i = tid; i < N; i += 1024)
        g_dinv[b][i] = rsqrtf((float)(g_deg[b][i] + 1));
}

// ---------------- per-branch x->fp16 convert + W transpose ----------------
__global__ __launch_bounds__(1024)
void k_cvt1(const float* __restrict__ x, const float* __restrict__ W,
            int b, int cvb, int total4) {
    __shared__ float smem_t[4][32][33];
    int bx = blockIdx.x;
    int tid = threadIdx.x;
    if ((int)bx < cvb) {
        long long li = (long long)bx * 1024 + tid;
        if (li < total4) {
            const float4* __restrict__ x4 = (const float4*)x;
            float4 v = __ldg(&x4[li]);
            __half2 h0 = __floats2half2_rn(v.x, v.y);
            __half2 h1 = __floats2half2_rn(v.z, v.w);
            uint2 u;
            u.x = *(uint32_t*)&h0; u.y = *(uint32_t*)&h1;
            ((uint2*)g_x16[b])[li] = u;
        }
    } else {
        int q = tid >> 8;
        int qt = tid & 255;
        int tileid = (bx - cvb) * 4 + q;      // 0..1023
        if (tileid < 1024) {
            int bxt = tileid & 31;
            int byt = tileid >> 5;
            int tx = qt & 31, ty = qt >> 5;
            int xg = bxt * 32 + tx;
            #pragma unroll
            for (int j = 0; j < 4; j++) {
                int y = byt * 32 + ty + j * 8;
                smem_t[q][ty + j * 8][tx] = W[(size_t)y * F + xg];
            }
            __syncthreads();
            int xo = byt * 32 + tx;
            #pragma unroll
            for (int j = 0; j < 4; j++) {
                int yo = bxt * 32 + ty + j * 8;
                g_wh[b][(size_t)yo * F + xo] = __float2half_rn(smem_t[q][tx][ty + j * 8]);
            }
        }
    }
}

// ---------------- per-branch CSR fill ----------------
__global__ void k_fill1(const void* __restrict__ ei, int E, int b, int slot) {
    int e = blockIdx.x * blockDim.x + threadIdx.x;
    if (e < E) {
        int is64 = g_is64[slot];
        int s = idx_at(ei, e, is64);
        int d = idx_at(ei, (long long)E + e, is64);
        int pos = atomicAdd(&g_cursor[b][d], 1);
        g_col[b][pos] = s;
    }
}

// ---------------- per-branch aggregation over row range [roff, ...) ----------------
// Also re-zeros g_deg[b][row] for the NEXT graph replay (deg is dead after scan).
__global__ void k_agg1(int b, int roff) {
    int row = roff + blockIdx.x;
    int t = threadIdx.x;
    if (t == 0) g_deg[b][row] = 0;     // recycle for next replay
    const uint2* __restrict__ x2v = (const uint2*)g_x16[b];
    const int* __restrict__ col = g_col[b];
    const float* __restrict__ dinv = g_dinv[b];
    float dv = dinv[row];
    uint2 xr = __ldg(&x2v[(size_t)row * 256 + t]);
    __half2 xr0 = *(__half2*)&xr.x, xr1 = *(__half2*)&xr.y;
    float w0 = dv * dv;
    float2 f0 = __half22float2(xr0), f1 = __half22float2(xr1);
    float4 acc;
    acc.x = f0.x * w0; acc.y = f0.y * w0; acc.z = f1.x * w0; acc.w = f1.y * w0;
    int s = g_rowptr[b][row], e = g_rowptr[b][row + 1];
    int j = s;
    for (; j + 4 <= e; j += 4) {
        int u0 = col[j], u1 = col[j + 1], u2 = col[j + 2], u3 = col[j + 3];
        float wa = dinv[u0] * dv, wb = dinv[u1] * dv;
        float wc = dinv[u2] * dv, wd = dinv[u3] * dv;
        uint2 v0 = __ldg(&x2v[(size_t)u0 * 256 + t]);
        uint2 v1 = __ldg(&x2v[(size_t)u1 * 256 + t]);
        uint2 v2 = __ldg(&x2v[(size_t)u2 * 256 + t]);
        uint2 v3 = __ldg(&x2v[(size_t)u3 * 256 + t]);
        float2 a0 = __half22float2(*(__half2*)&v0.x), a1 = __half22float2(*(__half2*)&v0.y);
        acc.x += a0.x * wa; acc.y += a0.y * wa; acc.z += a1.x * wa; acc.w += a1.y * wa;
        float2 b0 = __half22float2(*(__half2*)&v1.x), b1 = __half22float2(*(__half2*)&v1.y);
        acc.x += b0.x * wb; acc.y += b0.y * wb; acc.z += b1.x * wb; acc.w += b1.y * wb;
        float2 c0 = __half22float2(*(__half2*)&v2.x), c1 = __half22float2(*(__half2*)&v2.y);
        acc.x += c0.x * wc; acc.y += c0.y * wc; acc.z += c1.x * wc; acc.w += c1.y * wc;
        float2 d0 = __half22float2(*(__half2*)&v3.x), d1 = __half22float2(*(__half2*)&v3.y);
        acc.x += d0.x * wd; acc.y += d0.y * wd; acc.z += d1.x * wd; acc.w += d1.y * wd;
    }
    for (; j < e; j++) {
        int u = col[j];
        float w = dinv[u] * dv;
        uint2 xu = __ldg(&x2v[(size_t)u * 256 + t]);
        float2 g0 = __half22float2(*(__half2*)&xu.x), g1 = __half22float2(*(__half2*)&xu.y);
        acc.x += g0.x * w; acc.y += g0.y * w; acc.z += g1.x * w; acc.w += g1.y * w;
    }
    __half2 p0 = __floats2half2_rn(acc.x, acc.y);
    __half2 p1 = __floats2half2_rn(acc.z, acc.w);
    uint2 v;
    v.x = *(uint32_t*)&p0; v.y = *(uint32_t*)&p1;
    ((uint2*)g_a16[b])[(size_t)row * 256 + t] = v;
}

// ---------------- fp16 HMMA GEMM over M tile range ----------------
#define BK        64
#define NCHUNK    (F / BK)            // 16
#define ROWPAD    72                   // fp16 elems per smem row (64 data + 8 pad)
#define SA_BYTES  (128 * ROWPAD * 2)   // 18432 per tensor
#define STG_BYTES (2 * SA_BYTES)       // A, W
#define SM_TOT    (2 * STG_BYTES)      // 73728

__global__ __launch_bounds__(256, 2)
void k_tgemm(const float* __restrict__ bias, int M, int br, int mtoff) {
    extern __shared__ char smem[];
    uint32_t sb = smem_to_u32(smem);
    const __half* __restrict__ A  = g_a16[br];
    const __half* __restrict__ Wh = g_wh[br];

    int tid = threadIdx.x;
    int wid = tid >> 5, lane = tid & 31;
    int gid = lane >> 2, tig = lane & 3;
    int warp_m = wid & 1, warp_n = wid >> 1;
    int m0 = (mtoff + blockIdx.y) * 128;
    int n0 = blockIdx.x * 128;

    float acc[4][4][4];
    #pragma unroll
    for (int i = 0; i < 4; i++)
        #pragma unroll
        for (int j = 0; j < 4; j++)
            #pragma unroll
            for (int q = 0; q < 4; q++) acc[i][j][q] = 0.0f;

    auto load_chunk = [&](int c, int s) {
        uint32_t stg = sb + s * STG_BYTES;
        int k0 = c * BK;
        #pragma unroll
        for (int l = 0; l < 8; l++) {
            int idx = l * 256 + tid;
            int tsr = idx >> 10;          // 0 A, 1 W
            int rem = idx & 1023;
            int row = rem >> 3;
            int c16 = rem & 7;
            const __half* gsrc;
            bool pred = true;
            if (tsr == 0) {
                int grow = m0 + row;
                pred = grow < M;
                gsrc = A + (size_t)(pred ? grow : 0) * F + k0 + c16 * 8;
            } else {
                gsrc = Wh + (size_t)(n0 + row) * F + k0 + c16 * 8;
            }
            uint32_t sdst = stg + tsr * SA_BYTES + row * (ROWPAD * 2) + c16 * 16;
            cp_async16(sdst, gsrc, pred);
        }
        cp_commit();
    };

    load_chunk(0, 0);

    for (int c = 0; c < NCHUNK; c++) {
        int s = c & 1;
        if (c + 1 < NCHUNK) {
            load_chunk(c + 1, s ^ 1);
            cp_wait<1>();
        } else {
            cp_wait<0>();
        }
        __syncthreads();

        uint32_t sa  = sb + s * STG_BYTES;
        uint32_t sbh = sa + SA_BYTES;

        #pragma unroll
        for (int ks = 0; ks < 4; ks++) {
            int kb = ks * 16;
            uint32_t bh[4][2];
            #pragma unroll
            for (int nt = 0; nt < 4; nt++) {
                int n = warp_n * 32 + nt * 8 + gid;
                uint32_t o = n * (ROWPAD * 2) + (kb + tig * 2) * 2;
                bh[nt][0] = lds32(sbh + o);
                bh[nt][1] = lds32(sbh + o + 16);
            }
            #pragma unroll
            for (int mt = 0; mt < 4; mt++) {
                int r = warp_m * 64 + mt * 16 + gid;
                uint32_t o = r * (ROWPAD * 2) + (kb + tig * 2) * 2;
                uint32_t ah[4];
                ah[0] = lds32(sa + o);
                ah[1] = lds32(sa + o + 8 * (ROWPAD * 2));
                ah[2] = lds32(sa + o + 16);
                ah[3] = lds32(sa + o + 8 * (ROWPAD * 2) + 16);
                #pragma unroll
                for (int nt = 0; nt < 4; nt++) {
                    mma16816(acc[mt][nt], ah, bh[nt]);
                }
            }
        }
        __syncthreads();
    }

    __half* __restrict__ Y = g_y16[br];
    #pragma unroll
    for (int mt = 0; mt < 4; mt++) {
        int r0 = m0 + warp_m * 64 + mt * 16 + gid;
        #pragma unroll
        for (int nt = 0; nt < 4; nt++) {
            int col = n0 + warp_n * 32 + nt * 8 + tig * 2;
            float b0 = __ldg(&bias[col]);
            float b1 = __ldg(&bias[col + 1]);
            float* cf = acc[mt][nt];
            if (r0 < M) {
                __half2 v = __floats2half2_rn(leaky(cf[0] + b0), leaky(cf[1] + b1));
                *(__half2*)(Y + (size_t)r0 * F + col) = v;
            }
            if (r0 + 8 < M) {
                __half2 v = __floats2half2_rn(leaky(cf[2] + b0), leaky(cf[3] + b1));
                *(__half2*)(Y + (size_t)(r0 + 8) * F + col) = v;
            }
        }
    }
}

// ---------------- fused tail: pool + fc + final, one block per graph ----------------
__global__ __launch_bounds__(512)
void k_tail(const float* __restrict__ Wf0, const float* __restrict__ bf0,
            const float* __restrict__ Wf1, const float* __restrict__ bf1,
            const float* __restrict__ fW, const float* __restrict__ fb,
            float* __restrict__ out) {
    __shared__ float p[2][F];
    __shared__ float zr[256];
    int g = blockIdx.x;
    int tid = threadIdx.x;
    int b = tid >> 8, t = tid & 255;

    int s = g_goff[b][g], e = g_goff[b][g + 1];
    const __half2* __restrict__ Y2 = (const __half2*)g_y16[b];
    float2 s0 = {0.f, 0.f}, s1 = {0.f, 0.f};
    for (int r = s; r < e; r++) {
        float2 a = __half22float2(Y2[(size_t)r * 512 + t]);
        float2 c = __half22float2(Y2[(size_t)r * 512 + t + 256]);
        s0.x += a.x; s0.y += a.y; s1.x += c.x; s1.y += c.y;
    }
    float inv = 1.0f / fmaxf((float)(e - s), 1.0f);
    p[b][2 * t]             = s0.x * inv;
    p[b][2 * t + 1]         = s0.y * inv;
    p[b][2 * (t + 256)]     = s1.x * inv;
    p[b][2 * (t + 256) + 1] = s1.y * inv;
    __syncthreads();

    if (tid < 256) {
        int bb = tid >> 7, col = tid & 127;
        const float* __restrict__ Wf = bb ? Wf1 : Wf0;
        const float* __restrict__ bf = bb ? bf1 : bf0;
        float acc = 0.0f;
        #pragma unroll 8
        for (int k = 0; k < F; k++) acc += p[bb][k] * Wf[k * DD + col];
        acc += bf[col];
        zr[tid] = leaky(acc) * fW[tid];
    }
    __syncthreads();

    if (tid < 128) zr[tid] += zr[tid + 128];
    __syncthreads();
    if (tid < 64) zr[tid] += zr[tid + 64];
    __syncthreads();
    if (tid < 32) {
        float v = zr[tid] + zr[tid + 32];
        #pragma unroll
        for (int off = 16; off > 0; off >>= 1)
            v += __shfl_down_sync(0xFFFFFFFF, v, off);
        if (tid == 0) out[g] = v + fb[0];
    }
}

// ---------------- static streams/events for the pipelined graph ----------------
struct HxStreams {
    cudaStream_t q0 = 0, p1 = 0, q1 = 0;
    cudaEvent_t ePre = 0;
    cudaEvent_t eCvt[2] = {0, 0};
    cudaEvent_t eA0[2] = {0, 0}, eA1[2] = {0, 0};
    cudaEvent_t eG[2] = {0, 0};
    bool ok = false;
    HxStreams() {
        bool good = true;
        good &= cudaStreamCreateWithFlags(&q0, cudaStreamNonBlocking) == cudaSuccess;
        good &= cudaStreamCreateWithFlags(&p1, cudaStreamNonBlocking) == cudaSuccess;
        good &= cudaStreamCreateWithFlags(&q1, cudaStreamNonBlocking) == cudaSuccess;
        good &= cudaEventCreateWithFlags(&ePre, cudaEventDisableTiming) == cudaSuccess;
        for (int b = 0; b < 2; b++) {
            good &= cudaEventCreateWithFlags(&eCvt[b], cudaEventDisableTiming) == cudaSuccess;
            good &= cudaEventCreateWithFlags(&eA0[b], cudaEventDisableTiming) == cudaSuccess;
            good &= cudaEventCreateWithFlags(&eA1[b], cudaEventDisableTiming) == cudaSuccess;
            good &= cudaEventCreateWithFlags(&eG[b], cudaEventDisableTiming) == cudaSuccess;
        }
        ok = good;
    }
};
static HxStreams hx;

// ---------------- host launcher ----------------
extern "C" void kernel_launch(void* const* d_in, const int* in_sizes, int n_in,
                              void* d_out, int out_size) {
    const float* x1  = (const float*)d_in[0];
    const void*  ei1 = d_in[1];
    const void*  bt1 = d_in[2];
    const float* x2  = (const float*)d_in[3];
    const void*  ei2 = d_in[4];
    const void*  bt2 = d_in[5];
    int wb = n_in - 10;
    const float* c1W = (const float*)d_in[wb + 0];
    const float* c1b = (const float*)d_in[wb + 1];
    const float* f1W = (const float*)d_in[wb + 2];
    const float* f1b = (const float*)d_in[wb + 3];
    const float* c2W = (const float*)d_in[wb + 4];
    const float* c2b = (const float*)d_in[wb + 5];
    const float* f2W = (const float*)d_in[wb + 6];
    const float* f2b = (const float*)d_in[wb + 7];
    const float* fW  = (const float*)d_in[wb + 8];
    const float* fb  = (const float*)d_in[wb + 9];
    float* out = (float*)d_out;

    int N = in_sizes[0] / F;
    int E = in_sizes[1] / 2;

    const float* xs[2]  = {x1, x2};
    const void*  eis[2] = {ei1, ei2};
    const void*  bts[2] = {bt1, bt2};
    const float* cW[2]  = {c1W, c2W};
    const float* cb[2]  = {c1b, c2b};

    cudaFuncSetAttribute(k_tgemm, cudaFuncAttributeMaxDynamicSharedMemorySize, SM_TOT);

    int nbE = (E + 255) / 256;
    int total4 = N * (F / 4);
    int cvb = (total4 + 1023) / 1024;
    int mt = (N + 127) / 128;
    int mh0 = (mt + 1) / 2;
    int mh1 = mt - mh0;
    int rows0 = mh0 * 128; if (rows0 > N) rows0 = N;
    int rows1 = N - rows0;

    if (hx.ok) {
        cudaStream_t P[2] = {0, hx.p1};
        cudaStream_t Q[2] = {hx.q0, hx.q1};

        // pre (detection only, 4 blocks) on capture-origin stream, then fork
        k_pre<<<4, 256>>>((const unsigned int*)ei1, (const unsigned int*)bt1,
                          (const unsigned int*)ei2, (const unsigned int*)bt2,
                          2 * E, N, 2 * E, N);
        cudaEventRecord(hx.ePre, 0);
        cudaStreamWaitEvent(hx.p1, hx.ePre, 0);
        cudaStreamWaitEvent(hx.q0, hx.ePre, 0);
        cudaStreamWaitEvent(hx.q1, hx.ePre, 0);

        for (int b = 0; b < 2; b++) {
            k_cvt1<<<cvb + 256, 1024, 0, Q[b]>>>(xs[b], cW[b], b, cvb, total4);
            cudaEventRecord(hx.eCvt[b], Q[b]);
        }

        for (int b = 0; b < 2; b++) {
            k_deg1<<<nbE, 256, 0, P[b]>>>(eis[b], E, 2 * b, b);
            k_scan1<<<2, 1024, 0, P[b]>>>(N, b, bts[b], 2 * b + 1);
            k_fill1<<<nbE, 256, 0, P[b]>>>(eis[b], E, b, 2 * b);
            cudaStreamWaitEvent(P[b], hx.eCvt[b], 0);
            k_agg1<<<rows0, 256, 0, P[b]>>>(b, 0);
            cudaEventRecord(hx.eA0[b], P[b]);
            if (rows1 > 0) {
                k_agg1<<<rows1, 256, 0, P[b]>>>(b, rows0);
            }
            cudaEventRecord(hx.eA1[b], P[b]);
            cudaStreamWaitEvent(Q[b], hx.eA0[b], 0);
            k_tgemm<<<dim3(F / 128, mh0), 256, SM_TOT, Q[b]>>>(cb[b], N, b, 0);
            if (mh1 > 0) {
                cudaStreamWaitEvent(Q[b], hx.eA1[b], 0);
                k_tgemm<<<dim3(F / 128, mh1), 256, SM_TOT, Q[b]>>>(cb[b], N, b, mh0);
            }
            cudaEventRecord(hx.eG[b], Q[b]);
        }
        cudaStreamWaitEvent(0, hx.eA1[1], 0);
        cudaStreamWaitEvent(0, hx.eG[0], 0);
        cudaStreamWaitEvent(0, hx.eG[1], 0);
        k_tail<<<NG, 512>>>(f1W, f1b, f2W, f2b, fW, fb, out);
    } else {
        // fallback: sequential on legacy stream
        k_pre<<<4, 256>>>((const unsigned int*)ei1, (const unsigned int*)bt1,
                          (const unsigned int*)ei2, (const unsigned int*)bt2,
                          2 * E, N, 2 * E, N);
        for (int b = 0; b < 2; b++) {
            k_cvt1<<<cvb + 256, 1024>>>(xs[b], cW[b], b, cvb, total4);
            k_deg1<<<nbE, 256>>>(eis[b], E, 2 * b, b);
            k_scan1<<<2, 1024>>>(N, b, bts[b], 2 * b + 1);
            k_fill1<<<nbE, 256>>>(eis[b], E, b, 2 * b);
            k_agg1<<<N, 256>>>(b, 0);
            k_tgemm<<<dim3(F / 128, mt), 256, SM_TOT>>>(cb[b], N, b, 0);
        }
        k_tail<<<NG, 512>>>(f1W, f1b, f2W, f2b, fW, fb, out);
    }
}